// round 4
// baseline (speedup 1.0000x reference)
#include <cuda_runtime.h>
#include <cstdint>

// x:     [16, 64, 64, 128] f32        (32 MB)   — L2-pinned (evict_last)
// index: same shape, int64 or int32   (64/32 MB) — L2-pinned (evict_last)
// out:   [16, 128, 128, 128] f32      (128 MB)  — streamed (evict_first)
//
// Steady-state across graph replays: inputs (96 MB total) become L2-resident
// (126 MB L2), so per-replay DRAM traffic is just the mandatory 128 MB of
// output writes, which stream through L2 without evicting the pinned inputs.
//
// Each pooled element (b,h,w,c) owns the 4 cells of its 2x2 output block
// (bijection), so one thread writes all 4 cells: value where index matches,
// 0 elsewhere. No atomics, no zero pass, exact single coverage.
//
// Index dtype detected in-kernel: for LE int64 the 32-bit words 1,3,5,7 are
// high words of elements 0..3 (always 0, values < 2^31); for int32 they are
// index[1],[3],[5],[7] which are >= 1. Uniform branch, broadcast load.

#define PB 16
#define PH 64
#define PW 64
#define PC 128
#define OH 128
#define OW 128
#define N8 (PB * PH * PW * PC / 8)   // 1,048,576 vec8 elements

// ---- 256-bit memory ops (sm_100a+) with inverted L2 eviction policy ----

__device__ __forceinline__ void ldx8_pin(const float* p, float (&v)[8]) {
    asm("ld.global.nc.L2::evict_last.v8.f32 {%0,%1,%2,%3,%4,%5,%6,%7}, [%8];"
        : "=f"(v[0]), "=f"(v[1]), "=f"(v[2]), "=f"(v[3]),
          "=f"(v[4]), "=f"(v[5]), "=f"(v[6]), "=f"(v[7])
        : "l"(p));
}

__device__ __forceinline__ void ldi8_32_pin(const int* p, int (&v)[8]) {
    asm("ld.global.nc.L2::evict_last.v8.b32 {%0,%1,%2,%3,%4,%5,%6,%7}, [%8];"
        : "=r"(v[0]), "=r"(v[1]), "=r"(v[2]), "=r"(v[3]),
          "=r"(v[4]), "=r"(v[5]), "=r"(v[6]), "=r"(v[7])
        : "l"(p));
}

__device__ __forceinline__ void ldi4_64_pin(const void* p, long long (&v)[4]) {
    asm("ld.global.nc.L2::evict_last.v4.u64 {%0,%1,%2,%3}, [%4];"
        : "=l"(v[0]), "=l"(v[1]), "=l"(v[2]), "=l"(v[3])
        : "l"(p));
}

__device__ __forceinline__ void st8_stream(float* p, const float (&v)[8]) {
    asm volatile(
        "st.global.L2::evict_first.v8.f32 [%0], {%1,%2,%3,%4,%5,%6,%7,%8};"
        :: "l"(p),
           "f"(v[0]), "f"(v[1]), "f"(v[2]), "f"(v[3]),
           "f"(v[4]), "f"(v[5]), "f"(v[6]), "f"(v[7])
        : "memory");
}

__global__ void __launch_bounds__(256)
unpool_kernel(const float* __restrict__ x,
              const void*  __restrict__ idx_raw,
              float*       __restrict__ out)
{
    // --- in-kernel dtype detection (broadcast load, uniform branch) ---
    const uint4* hw = (const uint4*)idx_raw;
    const uint4 w0 = hw[0];                 // 32-bit words 0..3
    const uint4 w1 = hw[1];                 // 32-bit words 4..7
    const bool is64 = ((w0.y | w0.w | w1.y | w1.w) == 0u);

    const int j8 = blockIdx.x * blockDim.x + threadIdx.x;  // one vec8 per thread
    // j8 -> (b, h, w, c/8); PC/8 = 16
    const int cw = j8 & 15;
    int t = j8 >> 4;
    const int w = t & (PW - 1);
    t >>= 6;
    const int h = t & (PH - 1);
    const int b = t >> 6;
    const int base = (((b * OH + 2 * h) * OW) + 2 * w) * PC + 8 * cw;

    // front-batched independent loads (x: 32B, idx: 64B or 32B)
    float v[8];
    ldx8_pin(x + (size_t)j8 * 8, v);

    int ix[8];
    if (is64) {
        long long a[4], c[4];
        const char* p = (const char*)idx_raw + (size_t)j8 * 64;
        ldi4_64_pin(p, a);
        ldi4_64_pin(p + 32, c);
        #pragma unroll
        for (int k = 0; k < 4; k++) { ix[k] = (int)a[k]; ix[4 + k] = (int)c[k]; }
    } else {
        ldi8_32_pin((const int*)idx_raw + (size_t)j8 * 8, ix);
    }

    // 4 cells of the 2x2 block (all offsets multiples of 8 -> 32B aligned)
    const int offs[4] = {0, PC, OW * PC, OW * PC + PC};
    #pragma unroll
    for (int k = 0; k < 4; k++) {
        const int o = base + offs[k];
        float r[8];
        #pragma unroll
        for (int e = 0; e < 8; e++) r[e] = (ix[e] == o + e) ? v[e] : 0.0f;
        st8_stream(out + o, r);
    }
}

extern "C" void kernel_launch(void* const* d_in, const int* in_sizes, int n_in,
                              void* d_out, int out_size)
{
    const float* x   = (const float*)d_in[0];
    const void*  idx = d_in[1];
    float* out = (float*)d_out;

    const int threads = 256;
    const int blocks  = N8 / threads;        // 4096 blocks
    unpool_kernel<<<blocks, threads>>>(x, idx, out);
}